// round 14
// baseline (speedup 1.0000x reference)
#include <cuda_runtime.h>
#include <cuda_fp16.h>
#include <cstdint>
#include <cstddef>

#define Bq 64
#define Sq 1024
#define Dq 512
#define Hq 1024
#define NBLK 128
#define BSH ((size_t)Bq * Sq * Hq)

// ---------------- persistent device state ----------------
__device__ uint4 g_pack0u[(size_t)4096 * 1536 / 8];   // A fragment-packed weights L0
__device__ uint4 g_pack1u[(size_t)4096 * 2048 / 8];   // A fragment-packed weights L1
// B fragment-packed activations: uint4 idx = s*128 + ch2*64 + khalf*32 + lane
// u32[cg] = z[col = ch2*32+cg*8+(lane>>2)][k = s*16+khalf*8+(lane&3)*2 .. +1]
__device__ uint4 g_zx[(size_t)1024 * 4096];           // all x, pre-packed per t
__device__ uint4 g_zh0[2][8192];                      // h0, parity buffered
__device__ uint4 g_zh1[2][8192];                      // h1
__device__ float g_c0[Bq * Hq];                       // c state, [b][h]
__device__ float g_c1[Bq * Hq];
__device__ float g_bias0[4096];                       // bi+bh combined
__device__ float g_bias1[4096];
__device__ unsigned g_arrive[NBLK * 32];              // per-CTA arrive flags, 128B apart
__device__ unsigned g_gen2;

// ---------------- prep ----------------
__device__ __forceinline__ void pack_body(const float* __restrict__ Wa,
                                          const float* __restrict__ Wb,
                                          int Ka, int Kb, int NK, __half2* dst,
                                          int tid, int nth) {
    int total = 256 * NK * 128;
    for (int u = tid; u < total; u += nth) {
        int q2   = u & 3;
        int lane = (u >> 2) & 31;
        int rest = u >> 7;
        int s    = rest % NK;
        int t_id = rest / NK;
        int rl = (lane >> 2) + ((q2 & 1) << 3);
        int kl = ((lane & 3) << 1) + ((q2 & 2) << 2);
        int c = t_id >> 1, rh = t_id & 1;
        int r_cta = rh * 16 + rl;
        int row = (r_cta >> 3) * 1024 + c * 8 + (r_cta & 7);
        int kg = s * 16 + kl;
        float v0, v1;
        if (kg < Ka) {
            v0 = Wa[(size_t)row * Ka + kg];
            v1 = Wa[(size_t)row * Ka + kg + 1];
        } else {
            int kk = kg - Ka;
            v0 = Wb[(size_t)row * Kb + kk];
            v1 = Wb[(size_t)row * Kb + kk + 1];
        }
        dst[u] = __floats2half2_rn(v0, v1);
    }
}

__global__ void prep_kernel(const float* __restrict__ x,
                            const float* __restrict__ Wih0, const float* __restrict__ Whh0,
                            const float* __restrict__ bih0, const float* __restrict__ bhh0,
                            const float* __restrict__ Wih1, const float* __restrict__ Whh1,
                            const float* __restrict__ bih1, const float* __restrict__ bhh1) {
    int tid = blockIdx.x * blockDim.x + threadIdx.x;
    int nth = gridDim.x * blockDim.x;

    {   // x -> B-fragment-packed g_zx
        __half2* dst = reinterpret_cast<__half2*>(g_zx);
        const long total = (long)1024 * 16384;
        for (long u = tid; u < total; u += nth) {
            int cg    = (int)(u & 3);
            int lane  = (int)((u >> 2) & 31);
            int khalf = (int)((u >> 7) & 1);
            int ch2   = (int)((u >> 8) & 1);
            int s     = (int)((u >> 9) & 31);
            int t     = (int)(u >> 14);
            int b = ch2 * 32 + cg * 8 + (lane >> 2);
            int k = s * 16 + khalf * 8 + ((lane & 3) << 1);
            const float2 v = *reinterpret_cast<const float2*>(
                x + ((size_t)b * Sq + t) * Dq + k);
            dst[u] = __floats2half2_rn(v.x, v.y);
        }
    }
    pack_body(Wih0, Whh0, 512, 1024, 96, reinterpret_cast<__half2*>(g_pack0u), tid, nth);
    pack_body(Wih1, Whh1, 1024, 1024, 128, reinterpret_cast<__half2*>(g_pack1u), tid, nth);
    for (int i = tid; i < 4096; i += nth) {
        g_bias0[i] = bih0[i] + bhh0[i];
        g_bias1[i] = bih1[i] + bhh1[i];
    }
    {
        uint4 z4 = make_uint4(0, 0, 0, 0);
        for (int i = tid; i < 8192; i += nth) {
            g_zh0[1][i] = z4; g_zh1[1][i] = z4;
        }
        for (int i = tid; i < Bq * Hq; i += nth) { g_c0[i] = 0.0f; g_c1[i] = 0.0f; }
        for (int i = tid; i < NBLK * 32; i += nth) g_arrive[i] = 0u;
    }
    if (tid == 0) g_gen2 = 0u;
}

// ---------------- main persistent kernel ----------------
// gbuf: 16 warps x 32 lanes x 36 floats (16B-aligned stash, conflict-free STS.128)
#define PSTRIDE 36
#define SMEM_BYTES (16 * 32 * PSTRIDE * 4)

// Leader barrier: CTA0 gathers flags, broadcasts generation (one hot line)
__device__ __forceinline__ void grid_sync(unsigned target) {
    __syncthreads();
    __threadfence();
    const int tid = threadIdx.x;
    if (blockIdx.x == 0) {
        if (tid >= 1 && tid < NBLK) {
            unsigned v;
            do {
                asm volatile("ld.global.acquire.gpu.u32 %0, [%1];"
                             : "=r"(v) : "l"(g_arrive + tid * 32));
            } while (v < target);
        }
        __syncthreads();
        if (tid == 0)
            asm volatile("st.global.release.gpu.u32 [%0], %1;"
                         :: "l"(&g_gen2), "r"(target));
    } else {
        if (tid == 0) {
            asm volatile("st.global.release.gpu.u32 [%0], %1;"
                         :: "l"(g_arrive + blockIdx.x * 32), "r"(target));
            unsigned v;
            do {
                asm volatile("ld.global.acquire.gpu.u32 %0, [%1];"
                             : "=r"(v) : "l"(&g_gen2));
            } while (v < target);
        }
    }
    __syncthreads();
}

#define MMA16816(d, a, b0, b1)                                             \
    asm volatile("mma.sync.aligned.m16n8k16.row.col.f32.f16.f16.f32 "      \
                 "{%0,%1,%2,%3}, {%4,%5,%6,%7}, {%8,%9}, {%0,%1,%2,%3};\n" \
                 : "+f"((d)[0]), "+f"((d)[1]), "+f"((d)[2]), "+f"((d)[3])  \
                 : "r"((a).x), "r"((a).y), "r"((a).z), "r"((a).w),         \
                   "r"(b0), "r"(b1))

__device__ __forceinline__ float sigmf(float x) { return 1.0f / (1.0f + __expf(-x)); }
__device__ __forceinline__ float tanhfast(float x) {
    float e = __expf(2.0f * x);            // inf-safe
    return 1.0f - 2.0f / (e + 1.0f);
}

template <int L>
__device__ __forceinline__ void do_layer(int t, float* __restrict__ out) {
    extern __shared__ float gbuf[];
    const float* __restrict__ bias = L ? g_bias1 : g_bias0;
    const int tid = threadIdx.x, lane = tid & 31, w = tid >> 5;
    const int ch2 = w & 1, spl = w >> 1;              // 2 x 8
    const int cta = blockIdx.x;
    constexpr int NCH = L ? 8 : 6;
    constexpr int NK  = L ? 128 : 96;
    constexpr int NITER = 2 * NCH;
    const uint4* __restrict__ Abase =
        (L ? g_pack1u : g_pack0u) + ((size_t)(cta * 2) * NK) * 32 + lane;
    constexpr int astride = NK * 32;

    const int pcur = t & 1, pprev = (t + 1) & 1;

    // B chunk base tables (uniform, computed once)
    const uint4* __restrict__ zA;   // first source
    const uint4* __restrict__ zB;   // second source
    constexpr int CHSPLIT = L ? 4 : 2;
    if (L == 0) { zA = g_zx + (size_t)t * 4096; zB = g_zh0[pprev]; }
    else        { zA = g_zh0[pcur];             zB = g_zh1[pprev]; }
    const int boff = ch2 * 64 + lane;

    float acc[32];
#pragma unroll
    for (int i = 0; i < 32; i++) acc[i] = 0.f;

    // iteration i: ch = i>>1, sl = spl + (i&1)*8  (compile-time after unroll)
    uint4 ca0, ca1, cbl, cbh;
    {
        const uint4* Ac = Abase + spl * 32;
        const uint4* Bp = zA + boff + spl * 128;
        ca0 = __ldg(Ac); ca1 = __ldg(Ac + astride);
        cbl = __ldcg(Bp); cbh = __ldcg(Bp + 32);
    }
#pragma unroll
    for (int it = 0; it < NITER; ++it) {
        uint4 na0, na1, nbl, nbh;
        if (it + 1 < NITER) {
            const int ch = (it + 1) >> 1;
            const int sl = spl + ((it + 1) & 1) * 8;
            const uint4* Ac = Abase + (ch * 16 + sl) * 32;
            const uint4* Bp = (ch < CHSPLIT ? zA + ch * 2048
                                            : zB + (ch - CHSPLIT) * 2048) + boff + sl * 128;
            na0 = __ldg(Ac); na1 = __ldg(Ac + astride);
            nbl = __ldcg(Bp); nbh = __ldcg(Bp + 32);
        }
        MMA16816(acc +  0, ca0, cbl.x, cbh.x);        // tile (rh, cg) = rh*4+cg
        MMA16816(acc +  4, ca0, cbl.y, cbh.y);
        MMA16816(acc +  8, ca0, cbl.z, cbh.z);
        MMA16816(acc + 12, ca0, cbl.w, cbh.w);
        MMA16816(acc + 16, ca1, cbl.x, cbh.x);
        MMA16816(acc + 20, ca1, cbl.y, cbh.y);
        MMA16816(acc + 24, ca1, cbl.z, cbh.z);
        MMA16816(acc + 28, ca1, cbl.w, cbh.w);
        ca0 = na0; ca1 = na1; cbl = nbl; cbh = nbh;
    }

    // stash partials, vectorized (144B/lane stride -> 16B aligned, conflict-free)
    {
        float4* gw = reinterpret_cast<float4*>(gbuf + (w * 32 + lane) * PSTRIDE);
#pragma unroll
        for (int i = 0; i < 8; i++)
            gw[i] = make_float4(acc[i * 4], acc[i * 4 + 1], acc[i * 4 + 2], acc[i * 4 + 3]);
    }
    __syncthreads();

    // fused LSTM cell: thread -> (b = tid>>3, hp = tid&7)
    {
        const int b = tid >> 3, hp = tid & 7;
        const int hh = cta * 8 + hp;
        const int ch2e = b >> 5, b32 = b & 31, cg = b32 >> 3, coln = b32 & 7;
        float g4[4];
#pragma unroll
        for (int q = 0; q < 4; q++) {
            int rt  = q * 8 + hp;
            int rhe = rt >> 4, h16 = rt & 15;
            int Lr  = ((h16 & 7) << 2) | (coln >> 1);
            int r   = (coln & 1) + ((h16 >> 3) << 1);
            int tile = rhe * 4 + cg;
            int base = (ch2e * 32 + Lr) * PSTRIDE + tile * 4 + r;
            float s = bias[q * 1024 + hh];
#pragma unroll
            for (int sp = 0; sp < 8; sp++)
                s += gbuf[base + sp * (2 * 32 * PSTRIDE)];
            g4[q] = s;
        }
        float* cst = L ? g_c1 : g_c0;
        float cprev = cst[b * Hq + hh];
        float cn = sigmf(g4[1]) * cprev + sigmf(g4[0]) * tanhfast(g4[2]);
        float hn = sigmf(g4[3]) * tanhfast(cn);
        cst[b * Hq + hh] = cn;
        // scatter h into B-fragment-packed state
        {
            __half* zh = reinterpret_cast<__half*>(L ? g_zh1[pcur] : g_zh0[pcur]);
            int sf = hh >> 4, kh = (hh >> 3) & 1;
            int lz = ((b & 7) << 2) | ((hh >> 1) & 3);
            int cgz = (b >> 3) & 3;
            zh[(size_t)(((sf * 2 + ch2e) * 2 + kh) * 32 + lz) * 8 + cgz * 2 + (hh & 1)] =
                __float2half_rn(hn);
        }
        if (L) {
            size_t ob = (size_t)b * Sq * Hq + (size_t)t * Hq + hh;
            out[ob] = hn;
            out[BSH + ob] = cn;
            if (t == Sq - 1) {
                out[2 * BSH + (size_t)b * Hq + hh] = hn;
                out[2 * BSH + (size_t)Bq * Hq + (size_t)b * Hq + hh] = cn;
            }
        }
    }
    __syncthreads();
}

__global__ void __launch_bounds__(512, 1)
lstm_main(float* __restrict__ out) {
    // phase p: layer0 step p + layer1 step p-1, one grid barrier per phase
    do_layer<0>(0, out);
    grid_sync(1u);
    for (int p = 1; p < Sq; ++p) {
        do_layer<0>(p, out);
        do_layer<1>(p - 1, out);
        grid_sync((unsigned)(p + 1));
    }
    do_layer<1>(Sq - 1, out);
    grid_sync((unsigned)(Sq + 1));
}

// ---------------- launch ----------------
extern "C" void kernel_launch(void* const* d_in, const int* in_sizes, int n_in,
                              void* d_out, int out_size) {
    (void)in_sizes; (void)n_in; (void)out_size;
    const float* x    = (const float*)d_in[0];
    const float* Wih0 = (const float*)d_in[1];
    const float* Whh0 = (const float*)d_in[2];
    const float* bih0 = (const float*)d_in[3];
    const float* bhh0 = (const float*)d_in[4];
    const float* Wih1 = (const float*)d_in[5];
    const float* Whh1 = (const float*)d_in[6];
    const float* bih1 = (const float*)d_in[7];
    const float* bhh1 = (const float*)d_in[8];
    float* out = (float*)d_out;

    prep_kernel<<<4096, 256>>>(x, Wih0, Whh0, bih0, bhh0, Wih1, Whh1, bih1, bhh1);

    cudaFuncSetAttribute(lstm_main, cudaFuncAttributeMaxDynamicSharedMemorySize, SMEM_BYTES);
    lstm_main<<<NBLK, 512, SMEM_BYTES>>>(out);
}

// round 15
// speedup vs baseline: 1.0360x; 1.0360x over previous
#include <cuda_runtime.h>
#include <cuda_fp16.h>
#include <cstdint>
#include <cstddef>

#define Bq 64
#define Sq 1024
#define Dq 512
#define Hq 1024
#define NBLK 128
#define BSH ((size_t)Bq * Sq * Hq)

// ---------------- persistent device state ----------------
__device__ uint4 g_pack0u[(size_t)4096 * 1536 / 8];   // A fragment-packed weights L0
__device__ uint4 g_pack1u[(size_t)4096 * 2048 / 8];   // A fragment-packed weights L1
// B fragment-packed activations: uint4 idx = s*128 + ch2*64 + khalf*32 + lane
// u32[cg] = z[col = ch2*32+cg*8+(lane>>2)][k = s*16+khalf*8+(lane&3)*2 .. +1]
__device__ uint4 g_zx[(size_t)1024 * 4096];           // all x, pre-packed per t
__device__ uint4 g_zh0[2][8192];                      // h0, parity buffered
__device__ uint4 g_zh1[2][8192];                      // h1
__device__ float g_c0[Bq * Hq];                       // c state, [b][h]
__device__ float g_c1[Bq * Hq];
__device__ float g_bias0[4096];                       // bi+bh combined
__device__ float g_bias1[4096];
__device__ unsigned g_arrive[NBLK * 32];              // per-CTA arrive flags, 128B apart
__device__ unsigned g_gen2;

// ---------------- prep ----------------
__device__ __forceinline__ void pack_body(const float* __restrict__ Wa,
                                          const float* __restrict__ Wb,
                                          int Ka, int Kb, int NK, __half2* dst,
                                          int tid, int nth) {
    int total = 256 * NK * 128;
    for (int u = tid; u < total; u += nth) {
        int q2   = u & 3;
        int lane = (u >> 2) & 31;
        int rest = u >> 7;
        int s    = rest % NK;
        int t_id = rest / NK;
        int rl = (lane >> 2) + ((q2 & 1) << 3);
        int kl = ((lane & 3) << 1) + ((q2 & 2) << 2);
        int c = t_id >> 1, rh = t_id & 1;
        int r_cta = rh * 16 + rl;
        int row = (r_cta >> 3) * 1024 + c * 8 + (r_cta & 7);
        int kg = s * 16 + kl;
        float v0, v1;
        if (kg < Ka) {
            v0 = Wa[(size_t)row * Ka + kg];
            v1 = Wa[(size_t)row * Ka + kg + 1];
        } else {
            int kk = kg - Ka;
            v0 = Wb[(size_t)row * Kb + kk];
            v1 = Wb[(size_t)row * Kb + kk + 1];
        }
        dst[u] = __floats2half2_rn(v0, v1);
    }
}

__global__ void prep_kernel(const float* __restrict__ x,
                            const float* __restrict__ Wih0, const float* __restrict__ Whh0,
                            const float* __restrict__ bih0, const float* __restrict__ bhh0,
                            const float* __restrict__ Wih1, const float* __restrict__ Whh1,
                            const float* __restrict__ bih1, const float* __restrict__ bhh1) {
    int tid = blockIdx.x * blockDim.x + threadIdx.x;
    int nth = gridDim.x * blockDim.x;

    {   // x -> B-fragment-packed g_zx
        __half2* dst = reinterpret_cast<__half2*>(g_zx);
        const long total = (long)1024 * 16384;
        for (long u = tid; u < total; u += nth) {
            int cg    = (int)(u & 3);
            int lane  = (int)((u >> 2) & 31);
            int khalf = (int)((u >> 7) & 1);
            int ch2   = (int)((u >> 8) & 1);
            int s     = (int)((u >> 9) & 31);
            int t     = (int)(u >> 14);
            int b = ch2 * 32 + cg * 8 + (lane >> 2);
            int k = s * 16 + khalf * 8 + ((lane & 3) << 1);
            const float2 v = *reinterpret_cast<const float2*>(
                x + ((size_t)b * Sq + t) * Dq + k);
            dst[u] = __floats2half2_rn(v.x, v.y);
        }
    }
    pack_body(Wih0, Whh0, 512, 1024, 96, reinterpret_cast<__half2*>(g_pack0u), tid, nth);
    pack_body(Wih1, Whh1, 1024, 1024, 128, reinterpret_cast<__half2*>(g_pack1u), tid, nth);
    for (int i = tid; i < 4096; i += nth) {
        g_bias0[i] = bih0[i] + bhh0[i];
        g_bias1[i] = bih1[i] + bhh1[i];
    }
    {
        uint4 z4 = make_uint4(0, 0, 0, 0);
        for (int i = tid; i < 8192; i += nth) {
            g_zh0[1][i] = z4; g_zh1[1][i] = z4;
        }
        for (int i = tid; i < Bq * Hq; i += nth) { g_c0[i] = 0.0f; g_c1[i] = 0.0f; }
        for (int i = tid; i < NBLK * 32; i += nth) g_arrive[i] = 0u;
    }
    if (tid == 0) g_gen2 = 0u;
}

// ---------------- main persistent kernel ----------------
// gbuf: 16 warps x 32 lanes x 33 floats (pad) = 67584 B  (exact R9 stash)
#define PSTRIDE 33
#define SMEM_BYTES (16 * 32 * PSTRIDE * 4)

// Leader barrier: CTA0 gathers flags, broadcasts generation (one hot line)
__device__ __forceinline__ void grid_sync(unsigned target) {
    __syncthreads();
    __threadfence();
    const int tid = threadIdx.x;
    if (blockIdx.x == 0) {
        if (tid >= 1 && tid < NBLK) {
            unsigned v;
            do {
                asm volatile("ld.global.acquire.gpu.u32 %0, [%1];"
                             : "=r"(v) : "l"(g_arrive + tid * 32));
            } while (v < target);
        }
        __syncthreads();
        if (tid == 0)
            asm volatile("st.global.release.gpu.u32 [%0], %1;"
                         :: "l"(&g_gen2), "r"(target));
    } else {
        if (tid == 0) {
            asm volatile("st.global.release.gpu.u32 [%0], %1;"
                         :: "l"(g_arrive + blockIdx.x * 32), "r"(target));
            unsigned v;
            do {
                asm volatile("ld.global.acquire.gpu.u32 %0, [%1];"
                             : "=r"(v) : "l"(&g_gen2));
            } while (v < target);
        }
    }
    __syncthreads();
}

#define MMA16816(d, a, b0, b1)                                             \
    asm volatile("mma.sync.aligned.m16n8k16.row.col.f32.f16.f16.f32 "      \
                 "{%0,%1,%2,%3}, {%4,%5,%6,%7}, {%8,%9}, {%0,%1,%2,%3};\n" \
                 : "+f"((d)[0]), "+f"((d)[1]), "+f"((d)[2]), "+f"((d)[3])  \
                 : "r"((a).x), "r"((a).y), "r"((a).z), "r"((a).w),         \
                   "r"(b0), "r"(b1))

__device__ __forceinline__ float sigmf(float x) { return 1.0f / (1.0f + __expf(-x)); }
__device__ __forceinline__ float tanhfast(float x) {
    float e = __expf(2.0f * x);            // inf-safe
    return 1.0f - 2.0f / (e + 1.0f);
}

__device__ __forceinline__ void do_layer(int l, int t, float* __restrict__ out) {
    extern __shared__ float gbuf[];
    const float* __restrict__ bias = l ? g_bias1 : g_bias0;
    const int tid = threadIdx.x, lane = tid & 31, w = tid >> 5;
    const int ch2 = w & 1, spl = w >> 1;              // 2 x 8
    const int cta = blockIdx.x;
    const int NCH = l ? 8 : 6, NK = l ? 128 : 96;
    const uint4* __restrict__ Abase =
        (l ? g_pack1u : g_pack0u) + ((size_t)(cta * 2) * NK) * 32 + lane;
    const int astride = NK * 32;

    const int pcur = t & 1, pprev = (t + 1) & 1;

    float acc[32];
#pragma unroll
    for (int i = 0; i < 32; i++) acc[i] = 0.f;

    for (int ch = 0; ch < NCH; ++ch) {
        const uint4* __restrict__ Bp;
        if (l == 0) {
            if (ch < 2) Bp = g_zx + (size_t)t * 4096 + ch * 2048;
            else        Bp = g_zh0[pprev] + (ch - 2) * 2048;
        } else {
            if (ch < 4) Bp = g_zh0[pcur] + ch * 2048;
            else        Bp = g_zh1[pprev] + (ch - 4) * 2048;
        }
        Bp += ch2 * 64 + lane;
        const uint4* __restrict__ Ac = Abase + (ch * 16) * 32;
#pragma unroll
        for (int j = 0; j < 2; j++) {
            const int sl = spl + j * 8;
            uint4 a0 = __ldg(Ac + sl * 32);
            uint4 a1 = __ldg(Ac + sl * 32 + astride);
            uint4 bl = __ldcg(Bp + sl * 128);         // khalf 0 -> b0
            uint4 bh = __ldcg(Bp + sl * 128 + 32);    // khalf 1 -> b1
            MMA16816(acc +  0, a0, bl.x, bh.x);       // tile (rh, cg) = rh*4+cg
            MMA16816(acc +  4, a0, bl.y, bh.y);
            MMA16816(acc +  8, a0, bl.z, bh.z);
            MMA16816(acc + 12, a0, bl.w, bh.w);
            MMA16816(acc + 16, a1, bl.x, bh.x);
            MMA16816(acc + 20, a1, bl.y, bh.y);
            MMA16816(acc + 24, a1, bl.z, bh.z);
            MMA16816(acc + 28, a1, bl.w, bh.w);
        }
    }

    // stash partials (scalar, PSTRIDE 33 -> conflict-free; exact R9)
    float* gw = gbuf + (w * 32 + lane) * PSTRIDE;
#pragma unroll
    for (int i = 0; i < 32; i++) gw[i] = acc[i];
    __syncthreads();

    // fused LSTM cell: thread -> (b = tid>>3, hp = tid&7)
    {
        const int b = tid >> 3, hp = tid & 7;
        const int hh = cta * 8 + hp;
        const int ch2e = b >> 5, b32 = b & 31, cg = b32 >> 3, coln = b32 & 7;
        float g4[4];
#pragma unroll
        for (int q = 0; q < 4; q++) {
            int rt  = q * 8 + hp;
            int rhe = rt >> 4, h16 = rt & 15;
            int Lr  = ((h16 & 7) << 2) | (coln >> 1);
            int r   = (coln & 1) + ((h16 >> 3) << 1);
            int tile = rhe * 4 + cg;
            int base = (ch2e * 32 + Lr) * PSTRIDE + tile * 4 + r;
            float s = bias[q * 1024 + hh];
#pragma unroll
            for (int sp = 0; sp < 8; sp++)
                s += gbuf[base + sp * (2 * 32 * PSTRIDE)];
            g4[q] = s;
        }
        float* cst = l ? g_c1 : g_c0;
        float cprev = cst[b * Hq + hh];
        float cn = sigmf(g4[1]) * cprev + sigmf(g4[0]) * tanhfast(g4[2]);
        float hn = sigmf(g4[3]) * tanhfast(cn);
        cst[b * Hq + hh] = cn;
        // scatter h into B-fragment-packed state
        {
            __half* zh = reinterpret_cast<__half*>(l ? g_zh1[pcur] : g_zh0[pcur]);
            int sf = hh >> 4, kh = (hh >> 3) & 1;
            int lz = ((b & 7) << 2) | ((hh >> 1) & 3);
            int cgz = (b >> 3) & 3;
            zh[(size_t)(((sf * 2 + ch2e) * 2 + kh) * 32 + lz) * 8 + cgz * 2 + (hh & 1)] =
                __float2half_rn(hn);
        }
        if (l) {
            size_t ob = (size_t)b * Sq * Hq + (size_t)t * Hq + hh;
            __stcs(&out[ob], hn);                     // streaming: write-once data
            __stcs(&out[BSH + ob], cn);
            if (t == Sq - 1) {
                out[2 * BSH + (size_t)b * Hq + hh] = hn;
                out[2 * BSH + (size_t)Bq * Hq + (size_t)b * Hq + hh] = cn;
            }
        }
    }
    __syncthreads();
}

__global__ void __launch_bounds__(512, 1)
lstm_main(float* __restrict__ out) {
    // per-thread first-chunk addresses for L0 (constants: weights + x)
    const int tid = threadIdx.x, lane = tid & 31, w = tid >> 5;
    const int ch2 = w & 1, spl = w >> 1;
    const uint4* A0p = g_pack0u + ((size_t)(blockIdx.x * 2) * 96) * 32 + lane + spl * 32;
    const int boff = ch2 * 64 + lane + spl * 128;

    // phase p: layer0 step p + layer1 step p-1, one grid barrier per phase
    for (int p = 0; p <= Sq; ++p) {
        if (p < Sq)  do_layer(0, p,     out);
        if (p >= 1)  do_layer(1, p - 1, out);
        if (p + 1 < Sq) {
            // warm next phase's L0 first chunk during the barrier (no regs consumed)
            const uint4* xp = g_zx + (size_t)(p + 1) * 4096 + boff;
            asm volatile("prefetch.global.L1 [%0];" :: "l"(A0p));
            asm volatile("prefetch.global.L1 [%0];" :: "l"(A0p + 96 * 32));
            asm volatile("prefetch.global.L1 [%0];" :: "l"(A0p + 8 * 32));
            asm volatile("prefetch.global.L1 [%0];" :: "l"(A0p + 8 * 32 + 96 * 32));
            asm volatile("prefetch.global.L2 [%0];" :: "l"(xp));
            asm volatile("prefetch.global.L2 [%0];" :: "l"(xp + 32));
            asm volatile("prefetch.global.L2 [%0];" :: "l"(xp + 8 * 128));
            asm volatile("prefetch.global.L2 [%0];" :: "l"(xp + 8 * 128 + 32));
        }
        grid_sync((unsigned)(p + 1));
    }
}

// ---------------- launch ----------------
extern "C" void kernel_launch(void* const* d_in, const int* in_sizes, int n_in,
                              void* d_out, int out_size) {
    (void)in_sizes; (void)n_in; (void)out_size;
    const float* x    = (const float*)d_in[0];
    const float* Wih0 = (const float*)d_in[1];
    const float* Whh0 = (const float*)d_in[2];
    const float* bih0 = (const float*)d_in[3];
    const float* bhh0 = (const float*)d_in[4];
    const float* Wih1 = (const float*)d_in[5];
    const float* Whh1 = (const float*)d_in[6];
    const float* bih1 = (const float*)d_in[7];
    const float* bhh1 = (const float*)d_in[8];
    float* out = (float*)d_out;

    prep_kernel<<<4096, 256>>>(x, Wih0, Whh0, bih0, bhh0, Wih1, Whh1, bih1, bhh1);

    cudaFuncSetAttribute(lstm_main, cudaFuncAttributeMaxDynamicSharedMemorySize, SMEM_BYTES);
    lstm_main<<<NBLK, 512, SMEM_BYTES>>>(out);
}